// round 6
// baseline (speedup 1.0000x reference)
#include <cuda_runtime.h>
#include <math.h>
#include <stdint.h>

#define NN 8192
#define DD 128
#define KNN 10
#define KP1 11
#define ST 136                          // floats per smem tile row (544 B; %128B==32 -> LDS.64 conflict-free)
#define TILE_F (128 * ST)               // floats per [128x128] tile buffer
#define MST 89                          // merge-area row stride (gcd(356,128)=4 -> conflict-free)

// ---------------- device scratch (no allocation allowed) ----------------
__device__ __align__(16) float g_norm[2][NN];      // squared row norms
__device__ float g_ab[2][NN][KNN];                 // normalized knn dists (a, b)
__device__ float g_bpart[128];                     // sinkhorn block partials

// ======================= small PTX helpers ===============================
__device__ __forceinline__ uint32_t smem_u32(const void* p) {
    uint32_t a;
    asm("{ .reg .u64 t; cvta.to.shared.u64 t, %1; cvt.u32.u64 %0, t; }"
        : "=r"(a) : "l"(p));
    return a;
}

__device__ __forceinline__ void mma_tf32(float* c, float a0, float a1,
                                         float a2, float a3,
                                         float b0, float b1) {
    asm volatile(
        "mma.sync.aligned.m16n8k8.row.col.f32.tf32.tf32.f32 "
        "{%0,%1,%2,%3}, {%4,%5,%6,%7}, {%8,%9}, {%0,%1,%2,%3};"
        : "+f"(c[0]), "+f"(c[1]), "+f"(c[2]), "+f"(c[3])
        : "r"(__float_as_uint(a0)), "r"(__float_as_uint(a1)),
          "r"(__float_as_uint(a2)), "r"(__float_as_uint(a3)),
          "r"(__float_as_uint(b0)), "r"(__float_as_uint(b1)));
}

#define CP_ASYNC16(dst, src) \
    asm volatile("cp.async.cg.shared.global [%0], [%1], 16;" \
                 :: "r"(dst), "l"(src))
#define CP_COMMIT() asm volatile("cp.async.commit_group;" ::: "memory")
#define CP_WAIT0()  asm volatile("cp.async.wait_group 0;" ::: "memory")

// -------- dummy kernels: align dist kernel to profiled launch #4 --------
__global__ void dummy_kernel() {}

// ---------------- squared norms (warp per row) ---------------------------
__global__ void norms_kernel(const float* __restrict__ x0,
                             const float* __restrict__ x1) {
    const float* x = blockIdx.y ? x1 : x0;
    int row  = blockIdx.x * (blockDim.x >> 5) + (threadIdx.x >> 5);
    int lane = threadIdx.x & 31;
    float4 v = reinterpret_cast<const float4*>(x + (size_t)row * DD)[lane];
    float s = v.x * v.x + v.y * v.y + v.z * v.z + v.w * v.w;
#pragma unroll
    for (int o = 16; o; o >>= 1) s += __shfl_xor_sync(0xffffffffu, s, o);
    if (lane == 0) g_norm[blockIdx.y][row] = s;
}

// Insert v into descending-sorted 11-list (L[0] = largest kept)
__device__ __forceinline__ void insert11(float (&L)[KP1], float v) {
    if (v < L[0]) {
        L[0] = v;
#pragma unroll
        for (int i = 0; i < KP1 - 1; i++) {
            float lo = fminf(L[i], L[i + 1]);
            float hi = fmaxf(L[i], L[i + 1]);
            L[i] = hi; L[i + 1] = lo;
        }
    }
}

// async-copy one [128x128] B tile + its 128 norms into smem
__device__ __forceinline__ void cp_tile(float* dstB, float* dstN,
                                        const float* __restrict__ X,
                                        int t, int tid, int mat) {
    const float* src = X + (size_t)t * 128 * DD;
#pragma unroll
    for (int i = 0; i < 16; i++) {
        int c = tid + i * 256;                       // float4 chunk id
        int r = c >> 5, q = c & 31;
        uint32_t d = smem_u32(dstB + r * ST + q * 4);
        CP_ASYNC16(d, src + (size_t)r * DD + q * 4);
    }
    if (tid < 32) {
        uint32_t d = smem_u32(dstN + tid * 4);
        CP_ASYNC16(d, &g_norm[mat][t * 128 + tid * 4]);
    }
}

// ------ dist kernel: tf32 mma.sync Gram + per-row top-11 ----------------
// 256 thr = 8 warps. Warp w = (wm=w>>1, wn=w&1): rows wm*32..+31,
// cols wn*64..+63 of each [128x128] tile. Fragment loads are float2
// (LDS.64): smem k-positions (s*8+2tg, s*8+2tg+1) feed the MMA's
// (k=tg, k=tg+4) slots for BOTH A and B -> contraction order permuted
// consistently, result exact.
__global__ void __launch_bounds__(256, 1)
dist_knn_kernel(const float* __restrict__ x0, const float* __restrict__ x1) {
    extern __shared__ float sm[];
    float* sA   = sm;                        // [128][ST]
    float* sB   = sm + TILE_F;               // 2 x [128][ST]
    float* snrm = sm + 3 * TILE_F;           // 2 x [128]
    float* smrg = sB;                        // merge area aliases sB at end

    const int mat = blockIdx.y;
    const float* X = mat ? x1 : x0;
    const int r0 = blockIdx.x * 128;
    const int tid  = threadIdx.x;
    const int w    = tid >> 5;
    const int lane = tid & 31;
    const int g    = lane >> 2;              // 0..7
    const int tg   = lane & 3;               // 0..3
    const int wm   = w >> 1;                 // 0..3 -> row quadrant
    const int wn   = w & 1;                  // 0..1 -> col half

    // load A stripe [128 x 128] into padded smem (coalesced)
#pragma unroll
    for (int i = 0; i < 16; i++) {
        int c = tid + i * 256;
        int r = c >> 5, q = c & 31;
        float4 v = reinterpret_cast<const float4*>(X + (size_t)(r0 + r) * DD)[q];
        float* p = sA + r * ST + q * 4;
        p[0] = v.x; p[1] = v.y; p[2] = v.z; p[3] = v.w;
    }
    cp_tile(sB, snrm, X, 0, tid, mat);
    CP_COMMIT();
    __syncthreads();                         // sA visible

    // per-thread row pointers: rows wm*32 + {g, g+8, 16+g, 24+g}
    const float* paR[4];
    paR[0] = sA + (wm * 32 + g) * ST + 2 * tg;
    paR[1] = paR[0] + 8 * ST;
    paR[2] = paR[0] + 16 * ST;
    paR[3] = paR[0] + 24 * ST;

    float best[4][KP1];
#pragma unroll
    for (int r = 0; r < 4; r++)
#pragma unroll
        for (int i = 0; i < KP1; i++) best[r][i] = 1e30f;

    for (int t = 0; t < 64; t++) {
        const int p = t & 1;
        CP_WAIT0();
        __syncthreads();   // B(t)+norms(t) visible; buf p reads from t-1 done

        if (t + 1 < 64) {
            cp_tile(sB + (1 - p) * TILE_F, snrm + (1 - p) * 128,
                    X, t + 1, tid, mat);
            CP_COMMIT();
        }

        // lane's B row base: j = wn*64 + nt*8 + g
        const float* pbR = sB + p * TILE_F + (wn * 64 + g) * ST + 2 * tg;

        float acc[2][8][4];
#pragma unroll
        for (int m = 0; m < 2; m++)
#pragma unroll
            for (int n = 0; n < 8; n++) {
                acc[m][n][0] = 0.f; acc[m][n][1] = 0.f;
                acc[m][n][2] = 0.f; acc[m][n][3] = 0.f;
            }

#pragma unroll 4
        for (int s = 0; s < 16; s++) {
            const int ko = s * 8;
            float2 f0 = *reinterpret_cast<const float2*>(paR[0] + ko);
            float2 f1 = *reinterpret_cast<const float2*>(paR[1] + ko);
            float2 f2 = *reinterpret_cast<const float2*>(paR[2] + ko);
            float2 f3 = *reinterpret_cast<const float2*>(paR[3] + ko);
#pragma unroll
            for (int n = 0; n < 8; n++) {
                float2 b = *reinterpret_cast<const float2*>(pbR + n * 8 * ST + ko);
                mma_tf32(acc[0][n], f0.x, f1.x, f0.y, f1.y, b.x, b.y);
                mma_tf32(acc[1][n], f2.x, f3.x, f2.y, f3.y, b.x, b.y);
            }
        }

        // epilogue: key = sqb - 2*dot (same order as d^2)
        const float* nb = snrm + p * 128 + wn * 64 + 2 * tg;
#pragma unroll
        for (int n = 0; n < 8; n++) {
            float2 nv = *reinterpret_cast<const float2*>(nb + n * 8);
#pragma unroll
            for (int m = 0; m < 2; m++) {
                insert11(best[m * 2],     fmaf(-2.f, acc[m][n][0], nv.x));
                insert11(best[m * 2],     fmaf(-2.f, acc[m][n][1], nv.y));
                insert11(best[m * 2 + 1], fmaf(-2.f, acc[m][n][2], nv.x));
                insert11(best[m * 2 + 1], fmaf(-2.f, acc[m][n][3], nv.y));
            }
        }
    }

    __syncthreads();                         // all tile reads done; reuse sB
    // dump lists (ascending): row wm*32 + mt*16 + g + 8h, slot wn*4+tg
#pragma unroll
    for (int m = 0; m < 2; m++)
#pragma unroll
        for (int h = 0; h < 2; h++) {
            int rl = wm * 32 + m * 16 + g + 8 * h;
            float* L = smrg + rl * MST + (wn * 4 + tg) * KP1;
#pragma unroll
            for (int i = 0; i < KP1; i++)
                L[i] = best[m * 2 + h][KP1 - 1 - i];
        }
    __syncthreads();

    if (tid < 128) {
        const float* cand = smrg + tid * MST;      // 88 candidates
        float sel[KP1];
#pragma unroll
        for (int i = 0; i < KP1; i++) sel[i] = 1e30f;
        for (int q = 0; q < 8 * KP1; q++) insert11(sel, cand[q]);

        const int row = r0 + tid;
        const float sqa = g_norm[mat][row];
        float d[KP1];
#pragma unroll
        for (int i = 0; i < KP1; i++)
            d[i] = sqrtf(fmaxf(sel[i] + sqa, 1e-12f)); // descending; d[10]=self
        float sum = 0.f;
#pragma unroll
        for (int i = 0; i < KNN; i++) sum += d[i];
        float inv = 1.0f / (sum + 1e-10f);
#pragma unroll
        for (int j = 0; j < KNN; j++)
            g_ab[mat][row][j] = d[9 - j] * inv;        // ascending knn
    }
}

// -------- per-sample Sinkhorn (128 blocks x 64 thr) -----------------------
__global__ void __launch_bounds__(64, 1) sinkhorn_kernel() {
    const int row = blockIdx.x * 64 + threadIdx.x;     // 8192 threads

    float a[KNN], b[KNN], u[KNN], v[KNN], E[KNN], KM[KNN];
#pragma unroll
    for (int i = 0; i < KNN; i++) {
        a[i] = g_ab[0][row][i];
        b[i] = g_ab[1][row][i];
        u[i] = 1.0f;
    }
#pragma unroll
    for (int dd = 0; dd < KNN; dd++) {
        float m = (float)dd / 10.0f;
        E[dd]  = expf(-m / 0.1f);
        KM[dd] = E[dd] * m;
    }

    const float EPSf = 1e-10f;
#pragma unroll 1
    for (int it = 0; it < 50; it++) {
#pragma unroll
        for (int i = 0; i < KNN; i++) {
            float s = 0.f;
#pragma unroll
            for (int j = 0; j < KNN; j++)
                s = fmaf(E[i > j ? i - j : j - i], u[j], s);
            v[i] = __fdividef(b[i], s + EPSf);
        }
#pragma unroll
        for (int i = 0; i < KNN; i++) {
            float s = 0.f;
#pragma unroll
            for (int j = 0; j < KNN; j++)
                s = fmaf(E[i > j ? i - j : j - i], v[j], s);
            u[i] = __fdividef(a[i], s + EPSf);
        }
    }
#pragma unroll
    for (int i = 0; i < KNN; i++) {
        float s = 0.f;
#pragma unroll
        for (int j = 0; j < KNN; j++)
            s = fmaf(E[i > j ? i - j : j - i], u[j], s);
        v[i] = __fdividef(b[i], s + EPSf);
    }
    float cost = 0.f;
#pragma unroll
    for (int i = 0; i < KNN; i++) {
        float s = 0.f;
#pragma unroll
        for (int j = 0; j < KNN; j++) {
            int dd = i > j ? i - j : j - i;
            if (dd) s = fmaf(KM[dd], v[j], s);
        }
        cost = fmaf(u[i], s, cost);
    }

#pragma unroll
    for (int o = 16; o; o >>= 1) cost += __shfl_xor_sync(0xffffffffu, cost, o);
    __shared__ float ws[2];
    if ((threadIdx.x & 31) == 0) ws[threadIdx.x >> 5] = cost;
    __syncthreads();
    if (threadIdx.x == 0) g_bpart[blockIdx.x] = ws[0] + ws[1];
}

// -------- final deterministic reduction -> mean ---------------------------
__global__ void finalize_kernel(float* __restrict__ out) {
    float c = 0.f;
#pragma unroll
    for (int i = 0; i < 4; i++) c += g_bpart[threadIdx.x * 4 + i];
#pragma unroll
    for (int o = 16; o; o >>= 1) c += __shfl_xor_sync(0xffffffffu, c, o);
    if (threadIdx.x == 0) out[0] = c * (1.0f / 8192.0f);
}

// ------------------------------ launcher ---------------------------------
extern "C" void kernel_launch(void* const* d_in, const int* in_sizes, int n_in,
                              void* d_out, int out_size) {
    const float* x0 = (const float*)d_in[0];   // embeddings [8192,128]
    const float* x1 = (const float*)d_in[1];   // reference_embeddings
    float* out = (float*)d_out;

    // two no-op launches so the dist kernel is launch #4 (the one ncu grabs)
    dummy_kernel<<<1, 32>>>();
    dummy_kernel<<<1, 32>>>();

    norms_kernel<<<dim3(1024, 2), 256>>>(x0, x1);

    const int smem = (3 * TILE_F + 256) * (int)sizeof(float);   // ~210 KB
    cudaFuncSetAttribute(dist_knn_kernel,
                         cudaFuncAttributeMaxDynamicSharedMemorySize, smem);
    dist_knn_kernel<<<dim3(64, 2), 256, smem>>>(x0, x1);

    sinkhorn_kernel<<<128, 64>>>();
    finalize_kernel<<<1, 32>>>(out);
}

// round 7
// speedup vs baseline: 1.0316x; 1.0316x over previous
#include <cuda_runtime.h>
#include <math.h>
#include <stdint.h>

#define NN 8192
#define DD 128
#define KNN 10
#define KP1 11
#define ST 136                          // floats per smem tile row (544 B; %128B==32 -> LDS.64 conflict-free)
#define TILE_F (128 * ST)               // floats per [128x128] tile buffer
#define MST 177                         // merge-area row stride (16 lists * 11 + 1)

// ---------------- device scratch (no allocation allowed) ----------------
__device__ __align__(16) float g_norm[2][NN];      // squared row norms
__device__ float g_ab[2][NN][KNN];                 // normalized knn dists (a, b)
__device__ float g_bpart[128];                     // sinkhorn block partials

// ======================= small PTX helpers ===============================
__device__ __forceinline__ uint32_t smem_u32(const void* p) {
    uint32_t a;
    asm("{ .reg .u64 t; cvta.to.shared.u64 t, %1; cvt.u32.u64 %0, t; }"
        : "=r"(a) : "l"(p));
    return a;
}

__device__ __forceinline__ void mma_tf32(float* c, float a0, float a1,
                                         float a2, float a3,
                                         float b0, float b1) {
    asm volatile(
        "mma.sync.aligned.m16n8k8.row.col.f32.tf32.tf32.f32 "
        "{%0,%1,%2,%3}, {%4,%5,%6,%7}, {%8,%9}, {%0,%1,%2,%3};"
        : "+f"(c[0]), "+f"(c[1]), "+f"(c[2]), "+f"(c[3])
        : "r"(__float_as_uint(a0)), "r"(__float_as_uint(a1)),
          "r"(__float_as_uint(a2)), "r"(__float_as_uint(a3)),
          "r"(__float_as_uint(b0)), "r"(__float_as_uint(b1)));
}

#define CP_ASYNC16(dst, src) \
    asm volatile("cp.async.cg.shared.global [%0], [%1], 16;" \
                 :: "r"(dst), "l"(src))
#define CP_COMMIT() asm volatile("cp.async.commit_group;" ::: "memory")
#define CP_WAIT0()  asm volatile("cp.async.wait_group 0;" ::: "memory")

// -------- dummy kernels: align dist kernel to profiled launch #4 --------
__global__ void dummy_kernel() {}

// ---------------- squared norms (warp per row) ---------------------------
__global__ void norms_kernel(const float* __restrict__ x0,
                             const float* __restrict__ x1) {
    const float* x = blockIdx.y ? x1 : x0;
    int row  = blockIdx.x * (blockDim.x >> 5) + (threadIdx.x >> 5);
    int lane = threadIdx.x & 31;
    float4 v = reinterpret_cast<const float4*>(x + (size_t)row * DD)[lane];
    float s = v.x * v.x + v.y * v.y + v.z * v.z + v.w * v.w;
#pragma unroll
    for (int o = 16; o; o >>= 1) s += __shfl_xor_sync(0xffffffffu, s, o);
    if (lane == 0) g_norm[blockIdx.y][row] = s;
}

// Insert v into descending-sorted 11-list (L[0] = largest kept).
// The empty asm volatile blocks if-conversion: the 20-op sorting network
// must sit behind a real branch (taken ~57x per thread TOTAL, vs 2048 tests).
__device__ __forceinline__ void insert11(float (&L)[KP1], float v) {
    if (v < L[0]) {
        asm volatile("" ::: "memory");
        L[0] = v;
#pragma unroll
        for (int i = 0; i < KP1 - 1; i++) {
            float lo = fminf(L[i], L[i + 1]);
            float hi = fmaxf(L[i], L[i + 1]);
            L[i] = hi; L[i + 1] = lo;
        }
    }
}

// async-copy one [128x128] B tile + its 128 norms into smem (512 threads)
__device__ __forceinline__ void cp_tile(float* dstB, float* dstN,
                                        const float* __restrict__ X,
                                        int t, int tid, int mat) {
    const float* src = X + (size_t)t * 128 * DD;
#pragma unroll
    for (int i = 0; i < 8; i++) {
        int c = tid + i * 512;                       // float4 chunk id
        int r = c >> 5, q = c & 31;
        uint32_t d = smem_u32(dstB + r * ST + q * 4);
        CP_ASYNC16(d, src + (size_t)r * DD + q * 4);
    }
    if (tid < 32) {
        uint32_t d = smem_u32(dstN + tid * 4);
        CP_ASYNC16(d, &g_norm[mat][t * 128 + tid * 4]);
    }
}

// ------ dist kernel: tf32 mma.sync Gram + per-row top-11 ----------------
// 512 thr = 16 warps in a 4x4 grid: warp (wm=w>>2, wn=w&3) owns the
// 32x32 quadrant rows wm*32..+31, cols wn*32..+31 of each [128x128] tile.
// Fragment loads are float2 (LDS.64): smem k-positions (s*8+2tg, s*8+2tg+1)
// feed the MMA's (k=tg, k=tg+4) slots for BOTH A and B -> contraction order
// permuted consistently, result exact.
__global__ void __launch_bounds__(512, 1)
dist_knn_kernel(const float* __restrict__ x0, const float* __restrict__ x1) {
    extern __shared__ float sm[];
    float* sA   = sm;                        // [128][ST]
    float* sB   = sm + TILE_F;               // 2 x [128][ST]
    float* snrm = sm + 3 * TILE_F;           // 2 x [128]
    float* smrg = sB;                        // merge area aliases sB at end

    const int mat = blockIdx.y;
    const float* X = mat ? x1 : x0;
    const int r0 = blockIdx.x * 128;
    const int tid  = threadIdx.x;
    const int w    = tid >> 5;
    const int lane = tid & 31;
    const int g    = lane >> 2;              // 0..7
    const int tg   = lane & 3;               // 0..3
    const int wm   = w >> 2;                 // 0..3 -> row quadrant
    const int wn   = w & 3;                  // 0..3 -> col quadrant

    // load A stripe [128 x 128] into padded smem (coalesced)
#pragma unroll
    for (int i = 0; i < 8; i++) {
        int c = tid + i * 512;
        int r = c >> 5, q = c & 31;
        float4 v = reinterpret_cast<const float4*>(X + (size_t)(r0 + r) * DD)[q];
        float* p = sA + r * ST + q * 4;
        p[0] = v.x; p[1] = v.y; p[2] = v.z; p[3] = v.w;
    }
    cp_tile(sB, snrm, X, 0, tid, mat);
    CP_COMMIT();
    __syncthreads();                         // sA visible

    // per-thread A row pointers: rows wm*32 + {g, g+8, 16+g, 24+g}
    const float* paR[4];
    paR[0] = sA + (wm * 32 + g) * ST + 2 * tg;
    paR[1] = paR[0] + 8 * ST;
    paR[2] = paR[0] + 16 * ST;
    paR[3] = paR[0] + 24 * ST;

    float best[4][KP1];
#pragma unroll
    for (int r = 0; r < 4; r++)
#pragma unroll
        for (int i = 0; i < KP1; i++) best[r][i] = 1e30f;

    for (int t = 0; t < 64; t++) {
        const int p = t & 1;
        CP_WAIT0();
        __syncthreads();   // B(t)+norms(t) visible; all warps done with buf p

        if (t + 1 < 64) {
            cp_tile(sB + (1 - p) * TILE_F, snrm + (1 - p) * 128,
                    X, t + 1, tid, mat);
            CP_COMMIT();
        }

        // lane's B row base: j = wn*32 + n*8 + g
        const float* pbR = sB + p * TILE_F + (wn * 32 + g) * ST + 2 * tg;

        float acc[2][4][4];
#pragma unroll
        for (int m = 0; m < 2; m++)
#pragma unroll
            for (int n = 0; n < 4; n++) {
                acc[m][n][0] = 0.f; acc[m][n][1] = 0.f;
                acc[m][n][2] = 0.f; acc[m][n][3] = 0.f;
            }

#pragma unroll 4
        for (int s = 0; s < 16; s++) {
            const int ko = s * 8;
            float2 f0 = *reinterpret_cast<const float2*>(paR[0] + ko);
            float2 f1 = *reinterpret_cast<const float2*>(paR[1] + ko);
            float2 f2 = *reinterpret_cast<const float2*>(paR[2] + ko);
            float2 f3 = *reinterpret_cast<const float2*>(paR[3] + ko);
#pragma unroll
            for (int n = 0; n < 4; n++) {
                float2 b = *reinterpret_cast<const float2*>(pbR + n * 8 * ST + ko);
                mma_tf32(acc[0][n], f0.x, f1.x, f0.y, f1.y, b.x, b.y);
                mma_tf32(acc[1][n], f2.x, f3.x, f2.y, f3.y, b.x, b.y);
            }
        }

        // epilogue: key = sqb - 2*dot (same order as d^2)
        const float* nb = snrm + p * 128 + wn * 32 + 2 * tg;
#pragma unroll
        for (int n = 0; n < 4; n++) {
            float2 nv = *reinterpret_cast<const float2*>(nb + n * 8);
#pragma unroll
            for (int m = 0; m < 2; m++) {
                insert11(best[m * 2],     fmaf(-2.f, acc[m][n][0], nv.x));
                insert11(best[m * 2],     fmaf(-2.f, acc[m][n][1], nv.y));
                insert11(best[m * 2 + 1], fmaf(-2.f, acc[m][n][2], nv.x));
                insert11(best[m * 2 + 1], fmaf(-2.f, acc[m][n][3], nv.y));
            }
        }
    }

    __syncthreads();                         // all tile reads done; reuse sB
    // dump lists (ascending): row wm*32 + m*16 + g + 8h, slot wn*4+tg (of 16)
#pragma unroll
    for (int m = 0; m < 2; m++)
#pragma unroll
        for (int h = 0; h < 2; h++) {
            int rl = wm * 32 + m * 16 + g + 8 * h;
            float* L = smrg + rl * MST + (wn * 4 + tg) * KP1;
#pragma unroll
            for (int i = 0; i < KP1; i++)
                L[i] = best[m * 2 + h][KP1 - 1 - i];
        }
    __syncthreads();

    if (tid < 128) {
        const float* cand = smrg + tid * MST;      // 176 candidates
        float sel[KP1];
#pragma unroll
        for (int i = 0; i < KP1; i++) sel[i] = 1e30f;
        for (int q = 0; q < 16 * KP1; q++) insert11(sel, cand[q]);

        const int row = r0 + tid;
        const float sqa = g_norm[mat][row];
        float d[KP1];
#pragma unroll
        for (int i = 0; i < KP1; i++)
            d[i] = sqrtf(fmaxf(sel[i] + sqa, 1e-12f)); // descending; d[10]=self
        float sum = 0.f;
#pragma unroll
        for (int i = 0; i < KNN; i++) sum += d[i];
        float inv = 1.0f / (sum + 1e-10f);
#pragma unroll
        for (int j = 0; j < KNN; j++)
            g_ab[mat][row][j] = d[9 - j] * inv;        // ascending knn
    }
}

// -------- per-sample Sinkhorn (128 blocks x 64 thr) -----------------------
__global__ void __launch_bounds__(64, 1) sinkhorn_kernel() {
    const int row = blockIdx.x * 64 + threadIdx.x;     // 8192 threads

    float a[KNN], b[KNN], u[KNN], v[KNN], E[KNN], KM[KNN];
#pragma unroll
    for (int i = 0; i < KNN; i++) {
        a[i] = g_ab[0][row][i];
        b[i] = g_ab[1][row][i];
        u[i] = 1.0f;
    }
#pragma unroll
    for (int dd = 0; dd < KNN; dd++) {
        float m = (float)dd / 10.0f;
        E[dd]  = expf(-m / 0.1f);
        KM[dd] = E[dd] * m;
    }

    const float EPSf = 1e-10f;
#pragma unroll 1
    for (int it = 0; it < 50; it++) {
#pragma unroll
        for (int i = 0; i < KNN; i++) {
            float s = 0.f;
#pragma unroll
            for (int j = 0; j < KNN; j++)
                s = fmaf(E[i > j ? i - j : j - i], u[j], s);
            v[i] = __fdividef(b[i], s + EPSf);
        }
#pragma unroll
        for (int i = 0; i < KNN; i++) {
            float s = 0.f;
#pragma unroll
            for (int j = 0; j < KNN; j++)
                s = fmaf(E[i > j ? i - j : j - i], v[j], s);
            u[i] = __fdividef(a[i], s + EPSf);
        }
    }
#pragma unroll
    for (int i = 0; i < KNN; i++) {
        float s = 0.f;
#pragma unroll
        for (int j = 0; j < KNN; j++)
            s = fmaf(E[i > j ? i - j : j - i], u[j], s);
        v[i] = __fdividef(b[i], s + EPSf);
    }
    float cost = 0.f;
#pragma unroll
    for (int i = 0; i < KNN; i++) {
        float s = 0.f;
#pragma unroll
        for (int j = 0; j < KNN; j++) {
            int dd = i > j ? i - j : j - i;
            if (dd) s = fmaf(KM[dd], v[j], s);
        }
        cost = fmaf(u[i], s, cost);
    }

#pragma unroll
    for (int o = 16; o; o >>= 1) cost += __shfl_xor_sync(0xffffffffu, cost, o);
    __shared__ float ws[2];
    if ((threadIdx.x & 31) == 0) ws[threadIdx.x >> 5] = cost;
    __syncthreads();
    if (threadIdx.x == 0) g_bpart[blockIdx.x] = ws[0] + ws[1];
}

// -------- final deterministic reduction -> mean ---------------------------
__global__ void finalize_kernel(float* __restrict__ out) {
    float c = 0.f;
#pragma unroll
    for (int i = 0; i < 4; i++) c += g_bpart[threadIdx.x * 4 + i];
#pragma unroll
    for (int o = 16; o; o >>= 1) c += __shfl_xor_sync(0xffffffffu, c, o);
    if (threadIdx.x == 0) out[0] = c * (1.0f / 8192.0f);
}

// ------------------------------ launcher ---------------------------------
extern "C" void kernel_launch(void* const* d_in, const int* in_sizes, int n_in,
                              void* d_out, int out_size) {
    const float* x0 = (const float*)d_in[0];   // embeddings [8192,128]
    const float* x1 = (const float*)d_in[1];   // reference_embeddings
    float* out = (float*)d_out;

    // two no-op launches so the dist kernel is launch #4 (the one ncu grabs)
    dummy_kernel<<<1, 32>>>();
    dummy_kernel<<<1, 32>>>();

    norms_kernel<<<dim3(1024, 2), 256>>>(x0, x1);

    const int smem = (3 * TILE_F + 256) * (int)sizeof(float);   // ~210 KB
    cudaFuncSetAttribute(dist_knn_kernel,
                         cudaFuncAttributeMaxDynamicSharedMemorySize, smem);
    dist_knn_kernel<<<dim3(64, 2), 512, smem>>>(x0, x1);

    sinkhorn_kernel<<<128, 64>>>();
    finalize_kernel<<<1, 32>>>(out);
}

// round 8
// speedup vs baseline: 1.3224x; 1.2819x over previous
#include <cuda_runtime.h>
#include <cuda_bf16.h>
#include <math.h>
#include <stdint.h>

#define NN 8192
#define DD 128
#define KNN 10
#define KP1 11
#define RB 320                           // smem row stride in bytes (bf16 rows)

// ---------------- device scratch (no allocation allowed) ----------------
__device__ __align__(16) float g_norm[2][NN];            // squared row norms
__device__ __align__(16) __nv_bfloat162 g_xb[2][NN][64]; // bf16 copies of X
__device__ float g_ab[2][NN][KNN];                       // normalized knn dists
__device__ float g_bpart[128];                           // sinkhorn partials

// ======================= small PTX helpers ===============================
__device__ __forceinline__ uint32_t smem_u32(const void* p) {
    uint32_t a;
    asm("{ .reg .u64 t; cvta.to.shared.u64 t, %1; cvt.u32.u64 %0, t; }"
        : "=r"(a) : "l"(p));
    return a;
}

__device__ __forceinline__ void mma_bf16(float* c, uint32_t a0, uint32_t a1,
                                         uint32_t a2, uint32_t a3,
                                         uint32_t b0, uint32_t b1) {
    asm volatile(
        "mma.sync.aligned.m16n8k16.row.col.f32.bf16.bf16.f32 "
        "{%0,%1,%2,%3}, {%4,%5,%6,%7}, {%8,%9}, {%0,%1,%2,%3};"
        : "+f"(c[0]), "+f"(c[1]), "+f"(c[2]), "+f"(c[3])
        : "r"(a0), "r"(a1), "r"(a2), "r"(a3), "r"(b0), "r"(b1));
}

#define CP_ASYNC16(dst, src) \
    asm volatile("cp.async.cg.shared.global [%0], [%1], 16;" \
                 :: "r"(dst), "l"(src))
#define CP_COMMIT() asm volatile("cp.async.commit_group;" ::: "memory")
#define CP_WAIT0()  asm volatile("cp.async.wait_group 0;" ::: "memory")

// -------- dummy kernels: align dist kernel to profiled launch #4 --------
__global__ void dummy_kernel() {}

// ------ kernel: fused norms + fp32->bf16 conversion (warp per row) ------
__global__ void convnorm_kernel(const float* __restrict__ x0,
                                const float* __restrict__ x1) {
    const int mat = blockIdx.y;
    const float* x = mat ? x1 : x0;
    int row  = blockIdx.x * (blockDim.x >> 5) + (threadIdx.x >> 5);
    int lane = threadIdx.x & 31;
    float4 v = reinterpret_cast<const float4*>(x + (size_t)row * DD)[lane];
    float s = v.x * v.x + v.y * v.y + v.z * v.z + v.w * v.w;
#pragma unroll
    for (int o = 16; o; o >>= 1) s += __shfl_xor_sync(0xffffffffu, s, o);
    if (lane == 0) g_norm[mat][row] = s;
    g_xb[mat][row][lane * 2]     = __floats2bfloat162_rn(v.x, v.y);
    g_xb[mat][row][lane * 2 + 1] = __floats2bfloat162_rn(v.z, v.w);
}

// Insert v into descending-sorted 11-list (L[0] = largest kept).
// asm blocks if-conversion: the sort network sits behind a real branch.
__device__ __forceinline__ void insert11(float (&L)[KP1], float v) {
    if (v < L[0]) {
        asm volatile("" ::: "memory");
        L[0] = v;
#pragma unroll
        for (int i = 0; i < KP1 - 1; i++) {
            float lo = fminf(L[i], L[i + 1]);
            float hi = fmaxf(L[i], L[i + 1]);
            L[i] = hi; L[i + 1] = lo;
        }
    }
}

// async-copy one [128 x 256B] bf16 B tile + its 128 fp32 norms into smem
__device__ __forceinline__ void cp_tileB(char* dstB, float* dstN,
                                         int t, int tid, int mat) {
    const char* src = (const char*)&g_xb[mat][t * 128][0];
#pragma unroll
    for (int i = 0; i < 4; i++) {
        int idx = tid + i * 512;                 // 0..2047
        int r = idx >> 4, q = idx & 15;
        CP_ASYNC16(smem_u32(dstB + r * RB + q * 16), src + r * 256 + q * 16);
    }
    if (tid < 32)
        CP_ASYNC16(smem_u32((char*)dstN + tid * 16),
                   (const char*)&g_norm[mat][t * 128] + tid * 16);
}

// ------ dist kernel: bf16 m16n8k16 Gram + per-row top-11 ----------------
// 512 thr = 16 warps (wm=w>>2 rows 16*wm.., wn=w&3 cols 32*wn..) over a
// 64-row stripe x 128-col B tile. A/B fragments are contiguous LDS.128;
// the slot->k mapping is the same bijection for A and B, so the dot
// product over k is exact. 2 CTAs/SM (smem ~101 KB, <=64 regs).
__global__ void __launch_bounds__(512, 2)
dist_knn_kernel() {
    extern __shared__ char smc[];
    char*  sA   = smc;                       // 64 rows x RB    (20480 B)
    char*  sB   = smc + 20480;               // 2 x 128 x RB    (81920 B)
    float* snrm = (float*)(smc + 102400);    // 2 x 128 fp32

    const int mat = blockIdx.y;
    const int r0 = blockIdx.x * 64;
    const int tid  = threadIdx.x;
    const int w    = tid >> 5;
    const int lane = tid & 31;
    const int g    = lane >> 2;              // 0..7
    const int tg   = lane & 3;               // 0..3
    const int wm   = w >> 2;                 // 0..3 -> 16-row band
    const int wn   = w & 3;                  // 0..3 -> 32-col band

    // A stripe: 64 rows x 256B bf16 via cp.async
    {
        const char* srcA = (const char*)&g_xb[mat][r0][0];
#pragma unroll
        for (int i = 0; i < 2; i++) {
            int idx = tid + i * 512;             // 0..1023
            int r = idx >> 4, q = idx & 15;
            CP_ASYNC16(smem_u32(sA + r * RB + q * 16), srcA + r * 256 + q * 16);
        }
    }
    cp_tileB(sB, snrm, 0, tid, mat);
    CP_COMMIT();

    const char* pa0 = sA + (wm * 16 + g) * RB + 16 * tg;
    const char* pa1 = pa0 + 8 * RB;

    float best0[KP1], best1[KP1];
#pragma unroll
    for (int i = 0; i < KP1; i++) { best0[i] = 1e30f; best1[i] = 1e30f; }

    for (int t = 0; t < 64; t++) {
        const int p = t & 1;
        CP_WAIT0();
        __syncthreads();     // tile t + A visible; all warps done with buf p

        if (t + 1 < 64) {
            cp_tileB(sB + (1 - p) * 40960, snrm + (1 - p) * 128,
                     t + 1, tid, mat);
            CP_COMMIT();
        }

        const char* pb = sB + p * 40960 + (wn * 32 + g) * RB + 16 * tg;

        float acc[4][4];
#pragma unroll
        for (int n = 0; n < 4; n++) {
            acc[n][0] = 0.f; acc[n][1] = 0.f; acc[n][2] = 0.f; acc[n][3] = 0.f;
        }

#pragma unroll
        for (int ds = 0; ds < 4; ds++) {
            uint4 P = *reinterpret_cast<const uint4*>(pa0 + 64 * ds);
            uint4 Q = *reinterpret_cast<const uint4*>(pa1 + 64 * ds);
#pragma unroll
            for (int n = 0; n < 4; n++) {
                uint4 R = *reinterpret_cast<const uint4*>(pb + n * 8 * RB + 64 * ds);
                mma_bf16(acc[n], P.x, Q.x, P.y, Q.y, R.x, R.y);
                mma_bf16(acc[n], P.z, Q.z, P.w, Q.w, R.z, R.w);
            }
        }

        // epilogue: key = sqb - 2*dot (same order as d^2); batched test
        const float* nb = snrm + p * 128 + wn * 32 + 2 * tg;
#pragma unroll
        for (int n = 0; n < 4; n++) {
            float2 nv = *reinterpret_cast<const float2*>(nb + n * 8);
            float k0 = fmaf(-2.f, acc[n][0], nv.x);
            float k1 = fmaf(-2.f, acc[n][1], nv.y);
            float k2 = fmaf(-2.f, acc[n][2], nv.x);
            float k3 = fmaf(-2.f, acc[n][3], nv.y);
            if (fminf(k0, k1) < best0[0] || fminf(k2, k3) < best1[0]) {
                asm volatile("" ::: "memory");
                insert11(best0, k0); insert11(best0, k1);
                insert11(best1, k2); insert11(best1, k3);
            }
        }
    }

    __syncthreads();                         // all tile reads done; reuse sB
    // dump lists (ascending): row wm*16 + g + 8h, slot wn*4+tg (16 per row)
    {
        float* mrg = (float*)sB;             // 64 rows x 176 floats (45 KB)
        float* L0 = mrg + (wm * 16 + g) * 176 + (wn * 4 + tg) * KP1;
        float* L1 = L0 + 8 * 176;
#pragma unroll
        for (int i = 0; i < KP1; i++) {
            L0[i] = best0[KP1 - 1 - i];
            L1[i] = best1[KP1 - 1 - i];
        }
    }
    __syncthreads();

    if (tid < 64) {
        const float* cand = (float*)sB + tid * 176;    // 176 candidates
        float sel[KP1];
#pragma unroll
        for (int i = 0; i < KP1; i++) sel[i] = 1e30f;
        for (int q = 0; q < 16 * KP1; q++) insert11(sel, cand[q]);

        const int row = r0 + tid;
        const float sqa = g_norm[mat][row];
        float d[KP1];
#pragma unroll
        for (int i = 0; i < KP1; i++)
            d[i] = sqrtf(fmaxf(sel[i] + sqa, 1e-12f)); // descending; d[10]=self
        float sum = 0.f;
#pragma unroll
        for (int i = 0; i < KNN; i++) sum += d[i];
        float inv = 1.0f / (sum + 1e-10f);
#pragma unroll
        for (int j = 0; j < KNN; j++)
            g_ab[mat][row][j] = d[9 - j] * inv;        // ascending knn
    }
}

// -------- per-sample Sinkhorn (128 blocks x 64 thr) -----------------------
__global__ void __launch_bounds__(64, 1) sinkhorn_kernel() {
    const int row = blockIdx.x * 64 + threadIdx.x;     // 8192 threads

    float a[KNN], b[KNN], u[KNN], v[KNN], E[KNN], KM[KNN];
#pragma unroll
    for (int i = 0; i < KNN; i++) {
        a[i] = g_ab[0][row][i];
        b[i] = g_ab[1][row][i];
        u[i] = 1.0f;
    }
#pragma unroll
    for (int dd = 0; dd < KNN; dd++) {
        float m = (float)dd / 10.0f;
        E[dd]  = expf(-m / 0.1f);
        KM[dd] = E[dd] * m;
    }

    const float EPSf = 1e-10f;
#pragma unroll 1
    for (int it = 0; it < 50; it++) {
#pragma unroll
        for (int i = 0; i < KNN; i++) {
            float s = 0.f;
#pragma unroll
            for (int j = 0; j < KNN; j++)
                s = fmaf(E[i > j ? i - j : j - i], u[j], s);
            v[i] = __fdividef(b[i], s + EPSf);
        }
#pragma unroll
        for (int i = 0; i < KNN; i++) {
            float s = 0.f;
#pragma unroll
            for (int j = 0; j < KNN; j++)
                s = fmaf(E[i > j ? i - j : j - i], v[j], s);
            u[i] = __fdividef(a[i], s + EPSf);
        }
    }
#pragma unroll
    for (int i = 0; i < KNN; i++) {
        float s = 0.f;
#pragma unroll
        for (int j = 0; j < KNN; j++)
            s = fmaf(E[i > j ? i - j : j - i], u[j], s);
        v[i] = __fdividef(b[i], s + EPSf);
    }
    float cost = 0.f;
#pragma unroll
    for (int i = 0; i < KNN; i++) {
        float s = 0.f;
#pragma unroll
        for (int j = 0; j < KNN; j++) {
            int dd = i > j ? i - j : j - i;
            if (dd) s = fmaf(KM[dd], v[j], s);
        }
        cost = fmaf(u[i], s, cost);
    }

#pragma unroll
    for (int o = 16; o; o >>= 1) cost += __shfl_xor_sync(0xffffffffu, cost, o);
    __shared__ float ws[2];
    if ((threadIdx.x & 31) == 0) ws[threadIdx.x >> 5] = cost;
    __syncthreads();
    if (threadIdx.x == 0) g_bpart[blockIdx.x] = ws[0] + ws[1];
}

// -------- final deterministic reduction -> mean ---------------------------
__global__ void finalize_kernel(float* __restrict__ out) {
    float c = 0.f;
#pragma unroll
    for (int i = 0; i < 4; i++) c += g_bpart[threadIdx.x * 4 + i];
#pragma unroll
    for (int o = 16; o; o >>= 1) c += __shfl_xor_sync(0xffffffffu, c, o);
    if (threadIdx.x == 0) out[0] = c * (1.0f / 8192.0f);
}

// ------------------------------ launcher ---------------------------------
extern "C" void kernel_launch(void* const* d_in, const int* in_sizes, int n_in,
                              void* d_out, int out_size) {
    const float* x0 = (const float*)d_in[0];   // embeddings [8192,128]
    const float* x1 = (const float*)d_in[1];   // reference_embeddings
    float* out = (float*)d_out;

    // two no-op launches so the dist kernel is launch #4 (the one ncu grabs)
    dummy_kernel<<<1, 32>>>();
    dummy_kernel<<<1, 32>>>();

    convnorm_kernel<<<dim3(1024, 2), 256>>>(x0, x1);

    const int smem = 102400 + 1024;   // A + 2xB + norms = 103424 B (~101 KB)
    cudaFuncSetAttribute(dist_knn_kernel,
                         cudaFuncAttributeMaxDynamicSharedMemorySize, smem);
    dist_knn_kernel<<<dim3(128, 2), 512, smem>>>();

    sinkhorn_kernel<<<128, 64>>>();
    finalize_kernel<<<1, 32>>>(out);
}

// round 9
// speedup vs baseline: 1.6968x; 1.2831x over previous
#include <cuda_runtime.h>
#include <cuda_bf16.h>
#include <math.h>
#include <stdint.h>

#define NN 8192
#define DD 128
#define KNN 10
#define KP1 11
#define RB 320                           // smem row stride in bytes (bf16 rows)
#define SBB (128 * RB)                   // one B buffer = 40960 B
#define MST 89                           // merge row stride (8 lists * 11 + 1)

// ---------------- device scratch (no allocation allowed) ----------------
__device__ __align__(16) float g_norm[2][NN];            // squared row norms
__device__ __align__(16) __nv_bfloat162 g_xb[2][NN][64]; // bf16 copies of X
__device__ float g_ab[2][NN][KNN];                       // normalized knn dists
__device__ float g_bpart[128];                           // sinkhorn partials

// ======================= small PTX helpers ===============================
__device__ __forceinline__ uint32_t smem_u32(const void* p) {
    uint32_t a;
    asm("{ .reg .u64 t; cvta.to.shared.u64 t, %1; cvt.u32.u64 %0, t; }"
        : "=r"(a) : "l"(p));
    return a;
}

__device__ __forceinline__ void mma_bf16(float* c, uint32_t a0, uint32_t a1,
                                         uint32_t a2, uint32_t a3,
                                         uint32_t b0, uint32_t b1) {
    asm volatile(
        "mma.sync.aligned.m16n8k16.row.col.f32.bf16.bf16.f32 "
        "{%0,%1,%2,%3}, {%4,%5,%6,%7}, {%8,%9}, {%0,%1,%2,%3};"
        : "+f"(c[0]), "+f"(c[1]), "+f"(c[2]), "+f"(c[3])
        : "r"(a0), "r"(a1), "r"(a2), "r"(a3), "r"(b0), "r"(b1));
}

#define CP_ASYNC16(dst, src) \
    asm volatile("cp.async.cg.shared.global [%0], [%1], 16;" \
                 :: "r"(dst), "l"(src))
#define CP_COMMIT() asm volatile("cp.async.commit_group;" ::: "memory")
#define CP_WAIT0()  asm volatile("cp.async.wait_group 0;" ::: "memory")

// -------- dummy kernels: align dist kernel to profiled launch #4 --------
__global__ void dummy_kernel() {}

// ------ kernel: fused norms + fp32->bf16 conversion (warp per row) ------
__global__ void convnorm_kernel(const float* __restrict__ x0,
                                const float* __restrict__ x1) {
    const int mat = blockIdx.y;
    const float* x = mat ? x1 : x0;
    int row  = blockIdx.x * (blockDim.x >> 5) + (threadIdx.x >> 5);
    int lane = threadIdx.x & 31;
    float4 v = reinterpret_cast<const float4*>(x + (size_t)row * DD)[lane];
    float s = v.x * v.x + v.y * v.y + v.z * v.z + v.w * v.w;
#pragma unroll
    for (int o = 16; o; o >>= 1) s += __shfl_xor_sync(0xffffffffu, s, o);
    if (lane == 0) g_norm[mat][row] = s;
    g_xb[mat][row][lane * 2]     = __floats2bfloat162_rn(v.x, v.y);
    g_xb[mat][row][lane * 2 + 1] = __floats2bfloat162_rn(v.z, v.w);
}

// Insert v into descending-sorted 11-list (L[0] = largest kept).
// asm blocks if-conversion: the sort network sits behind a real branch.
__device__ __forceinline__ void insert11(float (&L)[KP1], float v) {
    if (v < L[0]) {
        asm volatile("" ::: "memory");
        L[0] = v;
#pragma unroll
        for (int i = 0; i < KP1 - 1; i++) {
            float lo = fminf(L[i], L[i + 1]);
            float hi = fmaxf(L[i], L[i + 1]);
            L[i] = hi; L[i + 1] = lo;
        }
    }
}

// async-copy one [128 x 256B] bf16 tile + its 128 fp32 norms into smem
__device__ __forceinline__ void cp_tileB(char* dstB, float* dstN,
                                         int t, int tid, int mat) {
    const char* src = (const char*)&g_xb[mat][t * 128][0];
#pragma unroll
    for (int i = 0; i < 4; i++) {
        int idx = tid + i * 512;                 // 0..2047
        int r = idx >> 4, q = idx & 15;
        CP_ASYNC16(smem_u32(dstB + r * RB + q * 16), src + r * 256 + q * 16);
    }
    if (tid < 32)
        CP_ASYNC16(smem_u32((char*)dstN + tid * 16),
                   (const char*)&g_norm[mat][t * 128] + tid * 16);
}

// ------ dist kernel: bf16 m16n8k16 Gram, A resident in registers --------
// 512 thr = 16 warps: wm=w>>1 (16-row band of the 128-row stripe),
// wn=w&1 (64-col half of the B tile). A fragments (k=128, m=16) live in
// 8 uint4 registers per thread, loaded ONCE; the 64-tile mainloop issues
// only B LDS.128 + HMMA. A and B share the same byte->k-slot bijection,
// so the contraction is exact. 1 CTA/SM, 128 regs, smem ~83 KB.
__global__ void __launch_bounds__(512, 1)
dist_knn_kernel() {
    extern __shared__ char smc[];
    char*  sB   = smc;                       // 2 x 128 x RB (81920 B)
    float* snrm = (float*)(smc + 2 * SBB);   // 2 x 128 fp32

    const int mat = blockIdx.y;
    const int r0 = blockIdx.x * 128;
    const int tid  = threadIdx.x;
    const int w    = tid >> 5;
    const int lane = tid & 31;
    const int g    = lane >> 2;              // 0..7
    const int tg   = lane & 3;               // 0..3
    const int wm   = w >> 1;                 // 0..7 -> 16-row band
    const int wn   = w & 1;                  // 0..1 -> 64-col half

    // ---- stage A stripe into sB0, load per-warp A fragments, release ----
    {
        const char* srcA = (const char*)&g_xb[mat][r0][0];
#pragma unroll
        for (int i = 0; i < 4; i++) {
            int idx = tid + i * 512;
            int r = idx >> 4, q = idx & 15;
            CP_ASYNC16(smem_u32(sB + r * RB + q * 16), srcA + r * 256 + q * 16);
        }
        CP_COMMIT(); CP_WAIT0();
        __syncthreads();
    }
    uint4 PA[4], QA[4];
    {
        const char* pa0 = sB + (wm * 16 + g) * RB + 16 * tg;
#pragma unroll
        for (int ds = 0; ds < 4; ds++) {
            PA[ds] = *reinterpret_cast<const uint4*>(pa0 + 64 * ds);
            QA[ds] = *reinterpret_cast<const uint4*>(pa0 + 8 * RB + 64 * ds);
        }
    }
    __syncthreads();                         // A reads done; sB0 reusable

    cp_tileB(sB, snrm, 0, tid, mat);
    CP_COMMIT();

    float best0[KP1], best1[KP1];
#pragma unroll
    for (int i = 0; i < KP1; i++) { best0[i] = 1e30f; best1[i] = 1e30f; }

    for (int t = 0; t < 64; t++) {
        const int p = t & 1;
        CP_WAIT0();
        __syncthreads();     // tile t visible; all warps done with buf p

        if (t + 1 < 64) {
            cp_tileB(sB + (1 - p) * SBB, snrm + (1 - p) * 128,
                     t + 1, tid, mat);
            CP_COMMIT();
        }

        const char* pb = sB + p * SBB + (wn * 64 + g) * RB + 16 * tg;

        float acc[8][4];
#pragma unroll
        for (int n = 0; n < 8; n++) {
            acc[n][0] = 0.f; acc[n][1] = 0.f; acc[n][2] = 0.f; acc[n][3] = 0.f;
        }

#pragma unroll
        for (int ds = 0; ds < 4; ds++) {
#pragma unroll
            for (int n = 0; n < 8; n++) {
                uint4 R = *reinterpret_cast<const uint4*>(pb + n * 8 * RB + 64 * ds);
                mma_bf16(acc[n], PA[ds].x, QA[ds].x, PA[ds].y, QA[ds].y, R.x, R.y);
                mma_bf16(acc[n], PA[ds].z, QA[ds].z, PA[ds].w, QA[ds].w, R.z, R.w);
            }
        }

        // epilogue: key = sqb - 2*dot (same order as d^2); batched test
        const float* nb = snrm + p * 128 + wn * 64 + 2 * tg;
#pragma unroll
        for (int n = 0; n < 8; n++) {
            float2 nv = *reinterpret_cast<const float2*>(nb + n * 8);
            float k0 = fmaf(-2.f, acc[n][0], nv.x);
            float k1 = fmaf(-2.f, acc[n][1], nv.y);
            float k2 = fmaf(-2.f, acc[n][2], nv.x);
            float k3 = fmaf(-2.f, acc[n][3], nv.y);
            if (fminf(k0, k1) < best0[0] || fminf(k2, k3) < best1[0]) {
                asm volatile("" ::: "memory");
                insert11(best0, k0); insert11(best0, k1);
                insert11(best1, k2); insert11(best1, k3);
            }
        }
    }

    __syncthreads();                         // all tile reads done; reuse sB
    // dump lists (ascending): row wm*16 + g + 8h, slot wn*4+tg (8 per row)
    {
        float* mrg = (float*)sB;             // 128 rows x MST floats (45.6 KB)
        float* L0 = mrg + (wm * 16 + g) * MST + (wn * 4 + tg) * KP1;
        float* L1 = L0 + 8 * MST;
#pragma unroll
        for (int i = 0; i < KP1; i++) {
            L0[i] = best0[KP1 - 1 - i];
            L1[i] = best1[KP1 - 1 - i];
        }
    }
    __syncthreads();

    if (tid < 128) {
        const float* cand = (float*)sB + tid * MST;    // 88 candidates
        float sel[KP1];
#pragma unroll
        for (int i = 0; i < KP1; i++) sel[i] = 1e30f;
        for (int q = 0; q < 8 * KP1; q++) insert11(sel, cand[q]);

        const int row = r0 + tid;
        const float sqa = g_norm[mat][row];
        float d[KP1];
#pragma unroll
        for (int i = 0; i < KP1; i++)
            d[i] = sqrtf(fmaxf(sel[i] + sqa, 1e-12f)); // descending; d[10]=self
        float sum = 0.f;
#pragma unroll
        for (int i = 0; i < KNN; i++) sum += d[i];
        float inv = 1.0f / (sum + 1e-10f);
#pragma unroll
        for (int j = 0; j < KNN; j++)
            g_ab[mat][row][j] = d[9 - j] * inv;        // ascending knn
    }
}

// -------- per-sample Sinkhorn (128 blocks x 64 thr) -----------------------
__global__ void __launch_bounds__(64, 1) sinkhorn_kernel() {
    const int row = blockIdx.x * 64 + threadIdx.x;     // 8192 threads

    float a[KNN], b[KNN], u[KNN], v[KNN], E[KNN], KM[KNN];
#pragma unroll
    for (int i = 0; i < KNN; i++) {
        a[i] = g_ab[0][row][i];
        b[i] = g_ab[1][row][i];
        u[i] = 1.0f;
    }
#pragma unroll
    for (int dd = 0; dd < KNN; dd++) {
        float m = (float)dd / 10.0f;
        E[dd]  = expf(-m / 0.1f);
        KM[dd] = E[dd] * m;
    }

    const float EPSf = 1e-10f;
#pragma unroll 1
    for (int it = 0; it < 50; it++) {
#pragma unroll
        for (int i = 0; i < KNN; i++) {
            float s = 0.f;
#pragma unroll
            for (int j = 0; j < KNN; j++)
                s = fmaf(E[i > j ? i - j : j - i], u[j], s);
            v[i] = __fdividef(b[i], s + EPSf);
        }
#pragma unroll
        for (int i = 0; i < KNN; i++) {
            float s = 0.f;
#pragma unroll
            for (int j = 0; j < KNN; j++)
                s = fmaf(E[i > j ? i - j : j - i], v[j], s);
            u[i] = __fdividef(a[i], s + EPSf);
        }
    }
#pragma unroll
    for (int i = 0; i < KNN; i++) {
        float s = 0.f;
#pragma unroll
        for (int j = 0; j < KNN; j++)
            s = fmaf(E[i > j ? i - j : j - i], u[j], s);
        v[i] = __fdividef(b[i], s + EPSf);
    }
    float cost = 0.f;
#pragma unroll
    for (int i = 0; i < KNN; i++) {
        float s = 0.f;
#pragma unroll
        for (int j = 0; j < KNN; j++) {
            int dd = i > j ? i - j : j - i;
            if (dd) s = fmaf(KM[dd], v[j], s);
        }
        cost = fmaf(u[i], s, cost);
    }

#pragma unroll
    for (int o = 16; o; o >>= 1) cost += __shfl_xor_sync(0xffffffffu, cost, o);
    __shared__ float ws[2];
    if ((threadIdx.x & 31) == 0) ws[threadIdx.x >> 5] = cost;
    __syncthreads();
    if (threadIdx.x == 0) g_bpart[blockIdx.x] = ws[0] + ws[1];
}

// -------- final deterministic reduction -> mean ---------------------------
__global__ void finalize_kernel(float* __restrict__ out) {
    float c = 0.f;
#pragma unroll
    for (int i = 0; i < 4; i++) c += g_bpart[threadIdx.x * 4 + i];
#pragma unroll
    for (int o = 16; o; o >>= 1) c += __shfl_xor_sync(0xffffffffu, c, o);
    if (threadIdx.x == 0) out[0] = c * (1.0f / 8192.0f);
}

// ------------------------------ launcher ---------------------------------
extern "C" void kernel_launch(void* const* d_in, const int* in_sizes, int n_in,
                              void* d_out, int out_size) {
    const float* x0 = (const float*)d_in[0];   // embeddings [8192,128]
    const float* x1 = (const float*)d_in[1];   // reference_embeddings
    float* out = (float*)d_out;

    // two no-op launches so the dist kernel is launch #4 (the one ncu grabs)
    dummy_kernel<<<1, 32>>>();
    dummy_kernel<<<1, 32>>>();

    convnorm_kernel<<<dim3(1024, 2), 256>>>(x0, x1);

    const int smem = 2 * SBB + 1024;   // 2 B buffers + norms = 82944 B
    cudaFuncSetAttribute(dist_knn_kernel,
                         cudaFuncAttributeMaxDynamicSharedMemorySize, smem);
    dist_knn_kernel<<<dim3(64, 2), 512, smem>>>();

    sinkhorn_kernel<<<128, 64>>>();
    finalize_kernel<<<1, 32>>>(out);
}